// round 2
// baseline (speedup 1.0000x reference)
#include <cuda_runtime.h>

#define EMBED_NUM 1024
#define EMBED_DIM 64
#define SPATIAL   32768          // 32*32*32
#define BATCH     4
#define NVEC      (BATCH * SPATIAL)   // 131072
#define CHUNK     128            // codes per smem tile (32 KB)
#define THREADS   256

__device__ float g_norms[EMBED_NUM];

// --------------------------------------------------------------------------
// Pre-pass: ||e_j||^2 for every codebook row (plain fp32 sequential sum).
// --------------------------------------------------------------------------
__global__ void vq_norms_kernel(const float* __restrict__ emb) {
    int j = blockIdx.x * blockDim.x + threadIdx.x;
    if (j < EMBED_NUM) {
        const float4* row = reinterpret_cast<const float4*>(emb + j * EMBED_DIM);
        float s = 0.f;
#pragma unroll
        for (int k = 0; k < EMBED_DIM / 4; k++) {
            float4 v = row[k];
            s += v.x * v.x + v.y * v.y + v.z * v.z + v.w * v.w;
        }
        g_norms[j] = s;
    }
}

// --------------------------------------------------------------------------
// Main kernel: one thread per spatial position.
//   x (64 fp32) in registers as 32 packed f32x2 values; xnorm = ||x||^2.
//   Codebook streamed through shared memory in 128-code chunks.
//   Distance replicates the JAX reference's fp32 rounding EXACTLY:
//       d_j = fsub_rn( fadd_rn(xnorm, ||e_j||^2), 2*dot_j )
//   The +xnorm (~64) quantizes d to ulp(64)=7.6e-6, absorbing dot-order
//   noise (~1e-9) so my argmin matches the reference's bit-for-bit.
// --------------------------------------------------------------------------
__global__ __launch_bounds__(THREADS)
void vq_argmin_kernel(const float* __restrict__ z,
                      const float* __restrict__ emb,
                      float* __restrict__ out) {
    __shared__ float4 se[CHUNK][EMBED_DIM / 4];   // 32 KB
    __shared__ float  snorm[CHUNK];

    const int n = blockIdx.x * blockDim.x + threadIdx.x;   // 0..131071
    const int b = n >> 15;                  // batch
    const int s = n & (SPATIAL - 1);        // spatial index
    const int base = b * (EMBED_DIM * SPATIAL) + s;

    // Load this position's 64-dim vector (stride SPATIAL between channels;
    // coalesced across the warp), pack into f32x2 registers, compute ||x||^2.
    unsigned long long xp[EMBED_DIM / 2];
    float xnorm = 0.f;
#pragma unroll
    for (int k = 0; k < EMBED_DIM; k += 2) {
        float a = z[base + k * SPATIAL];
        float c = z[base + (k + 1) * SPATIAL];
        xnorm = __fadd_rn(xnorm, __fmul_rn(a, a));
        xnorm = __fadd_rn(xnorm, __fmul_rn(c, c));
        asm("mov.b64 %0, {%1, %2};" : "=l"(xp[k >> 1]) : "f"(a), "f"(c));
    }

    float best = 3.4e38f;
    int   bidx = 0;

    for (int c0 = 0; c0 < EMBED_NUM; c0 += CHUNK) {
        // Cooperative chunk load: CHUNK*64 floats = 2048 float4, 8 per thread.
        {
            const float4* src = reinterpret_cast<const float4*>(emb + c0 * EMBED_DIM);
            float4* dst = &se[0][0];
#pragma unroll
            for (int i = threadIdx.x; i < CHUNK * (EMBED_DIM / 4); i += THREADS)
                dst[i] = src[i];
            if (threadIdx.x < CHUNK)
                snorm[threadIdx.x] = g_norms[c0 + threadIdx.x];
        }
        __syncthreads();

#pragma unroll 1
        for (int j = 0; j < CHUNK; j += 2) {
            const ulonglong2* e0 = reinterpret_cast<const ulonglong2*>(&se[j][0]);
            const ulonglong2* e1 = reinterpret_cast<const ulonglong2*>(&se[j + 1][0]);
            unsigned long long a0 = 0ULL, a1 = 0ULL;   // code j   accumulators
            unsigned long long b0 = 0ULL, b1 = 0ULL;   // code j+1 accumulators
#pragma unroll
            for (int q = 0; q < EMBED_DIM / 4; q++) {  // 16 iterations
                ulonglong2 v0 = e0[q];                 // LDS.128 (broadcast)
                ulonglong2 v1 = e1[q];
                asm("fma.rn.f32x2 %0, %1, %2, %0;" : "+l"(a0) : "l"(xp[2 * q]),     "l"(v0.x));
                asm("fma.rn.f32x2 %0, %1, %2, %0;" : "+l"(b0) : "l"(xp[2 * q]),     "l"(v1.x));
                asm("fma.rn.f32x2 %0, %1, %2, %0;" : "+l"(a1) : "l"(xp[2 * q + 1]), "l"(v0.y));
                asm("fma.rn.f32x2 %0, %1, %2, %0;" : "+l"(b1) : "l"(xp[2 * q + 1]), "l"(v1.y));
            }
            float a0l, a0h, a1l, a1h, b0l, b0h, b1l, b1h;
            asm("mov.b64 {%0, %1}, %2;" : "=f"(a0l), "=f"(a0h) : "l"(a0));
            asm("mov.b64 {%0, %1}, %2;" : "=f"(a1l), "=f"(a1h) : "l"(a1));
            asm("mov.b64 {%0, %1}, %2;" : "=f"(b0l), "=f"(b0h) : "l"(b0));
            asm("mov.b64 {%0, %1}, %2;" : "=f"(b1l), "=f"(b1h) : "l"(b1));
            float dot0 = (a0l + a0h) + (a1l + a1h);
            float dot1 = (b0l + b0h) + (b1l + b1h);
            // Reference-exact fp32 rounding: (xnorm + ||e||^2) - 2*dot
            float d0 = __fsub_rn(__fadd_rn(xnorm, snorm[j]),
                                 __fmul_rn(2.0f, dot0));
            float d1 = __fsub_rn(__fadd_rn(xnorm, snorm[j + 1]),
                                 __fmul_rn(2.0f, dot1));
            // strict < keeps the earliest index on ties (matches jnp.argmin)
            if (d0 < best) { best = d0; bidx = c0 + j; }
            if (d1 < best) { best = d1; bidx = c0 + j + 1; }
        }
        __syncthreads();
    }

    // Gather the winning code (L2-resident) and scatter to channel-strided out.
    const float4* erow = reinterpret_cast<const float4*>(emb + bidx * EMBED_DIM);
#pragma unroll
    for (int k = 0; k < EMBED_DIM / 4; k++) {
        float4 v = erow[k];
        out[base + (4 * k + 0) * SPATIAL] = v.x;
        out[base + (4 * k + 1) * SPATIAL] = v.y;
        out[base + (4 * k + 2) * SPATIAL] = v.z;
        out[base + (4 * k + 3) * SPATIAL] = v.w;
    }
}

// --------------------------------------------------------------------------
extern "C" void kernel_launch(void* const* d_in, const int* in_sizes, int n_in,
                              void* d_out, int out_size) {
    const float* z   = (const float*)d_in[0];
    const float* emb = (const float*)d_in[1];
    // robustness: identify codebook by element count (1024*64 = 65536)
    if (n_in >= 2 && in_sizes[0] == EMBED_NUM * EMBED_DIM &&
        in_sizes[1] != EMBED_NUM * EMBED_DIM) {
        z   = (const float*)d_in[1];
        emb = (const float*)d_in[0];
    }
    float* out = (float*)d_out;

    vq_norms_kernel<<<(EMBED_NUM + 255) / 256, 256>>>(emb);
    vq_argmin_kernel<<<NVEC / THREADS, THREADS>>>(z, emb, out);
}

// round 3
// speedup vs baseline: 1.2982x; 1.2982x over previous
#include <cuda_runtime.h>

#define EMBED_NUM 1024
#define EMBED_DIM 64
#define SPATIAL   32768          // 32*32*32
#define BATCH     4
#define NVEC      (BATCH * SPATIAL)   // 131072
#define CHUNK     128            // codes per smem tile (32 KB)
#define THREADS   128
#define PPT       2              // positions per thread (register-blocked)

__device__ float g_norms[EMBED_NUM];

// --------------------------------------------------------------------------
// Pre-pass: ||e_j||^2 for every codebook row (plain fp32 sequential sum).
// --------------------------------------------------------------------------
__global__ void vq_norms_kernel(const float* __restrict__ emb) {
    int j = blockIdx.x * blockDim.x + threadIdx.x;
    if (j < EMBED_NUM) {
        const float4* row = reinterpret_cast<const float4*>(emb + j * EMBED_DIM);
        float s = 0.f;
#pragma unroll
        for (int k = 0; k < EMBED_DIM / 4; k++) {
            float4 v = row[k];
            s += v.x * v.x + v.y * v.y + v.z * v.z + v.w * v.w;
        }
        g_norms[j] = s;
    }
}

// --------------------------------------------------------------------------
// Main kernel: one thread handles PPT=2 spatial positions.
//   Each code float4 loaded from smem now feeds 2 positions' dot products:
//   LDS instructions per FMA halve vs R2 (which was L1-pipe-bound at 81%).
//   Distance replicates the JAX reference's fp32 rounding EXACTLY (same
//   chain structure and reduction order as the R2 kernel, rel_err == 0.0):
//       d = fsub_rn( fadd_rn(xnorm, ||e||^2), fmul_rn(2, dot) )
// --------------------------------------------------------------------------
__global__ __launch_bounds__(THREADS, 2)
void vq_argmin_kernel(const float* __restrict__ z,
                      const float* __restrict__ emb,
                      float* __restrict__ out) {
    __shared__ float4 se[CHUNK][EMBED_DIM / 4];   // 32 KB
    __shared__ float  snorm[CHUNK];

    // Block covers 256 consecutive positions; thread t owns t and t+128.
    // 256 | 32768 so both positions are always in the same batch.
    const int p0 = blockIdx.x * (THREADS * PPT) + threadIdx.x;
    const int p1 = p0 + THREADS;
    const int b  = p0 >> 15;
    const int base0 = b * (EMBED_DIM * SPATIAL) + (p0 & (SPATIAL - 1));
    const int base1 = b * (EMBED_DIM * SPATIAL) + (p1 & (SPATIAL - 1));

    // Load both positions' 64-dim vectors (coalesced channel-strided loads),
    // pack into f32x2 registers, compute ||x||^2 each.
    unsigned long long x0[EMBED_DIM / 2], x1[EMBED_DIM / 2];
    float xn0 = 0.f, xn1 = 0.f;
#pragma unroll
    for (int k = 0; k < EMBED_DIM; k += 2) {
        float a = z[base0 + k * SPATIAL];
        float c = z[base0 + (k + 1) * SPATIAL];
        xn0 = __fadd_rn(xn0, __fmul_rn(a, a));
        xn0 = __fadd_rn(xn0, __fmul_rn(c, c));
        asm("mov.b64 %0, {%1, %2};" : "=l"(x0[k >> 1]) : "f"(a), "f"(c));
        float d = z[base1 + k * SPATIAL];
        float e = z[base1 + (k + 1) * SPATIAL];
        xn1 = __fadd_rn(xn1, __fmul_rn(d, d));
        xn1 = __fadd_rn(xn1, __fmul_rn(e, e));
        asm("mov.b64 %0, {%1, %2};" : "=l"(x1[k >> 1]) : "f"(d), "f"(e));
    }

    float best0 = 3.4e38f, best1 = 3.4e38f;
    int   bi0 = 0, bi1 = 0;

    for (int c0 = 0; c0 < EMBED_NUM; c0 += CHUNK) {
        // Cooperative chunk load: 2048 float4, 16 per thread.
        {
            const float4* src = reinterpret_cast<const float4*>(emb + c0 * EMBED_DIM);
            float4* dst = &se[0][0];
#pragma unroll
            for (int i = threadIdx.x; i < CHUNK * (EMBED_DIM / 4); i += THREADS)
                dst[i] = src[i];
            if (threadIdx.x < CHUNK)
                snorm[threadIdx.x] = g_norms[c0 + threadIdx.x];
        }
        __syncthreads();

#pragma unroll 1
        for (int j = 0; j < CHUNK; j += 2) {
            const ulonglong2* e0 = reinterpret_cast<const ulonglong2*>(&se[j][0]);
            const ulonglong2* e1 = reinterpret_cast<const ulonglong2*>(&se[j + 1][0]);
            // acc[pos][code][half]
            unsigned long long a00 = 0ULL, a01 = 0ULL;  // pos0, code j
            unsigned long long a10 = 0ULL, a11 = 0ULL;  // pos0, code j+1
            unsigned long long b00 = 0ULL, b01 = 0ULL;  // pos1, code j
            unsigned long long b10 = 0ULL, b11 = 0ULL;  // pos1, code j+1
#pragma unroll
            for (int q = 0; q < EMBED_DIM / 4; q++) {  // 16 iterations
                ulonglong2 v0 = e0[q];                 // LDS.128 broadcast
                ulonglong2 v1 = e1[q];
                unsigned long long xa0 = x0[2 * q], xa1 = x0[2 * q + 1];
                unsigned long long xb0 = x1[2 * q], xb1 = x1[2 * q + 1];
                asm("fma.rn.f32x2 %0, %1, %2, %0;" : "+l"(a00) : "l"(xa0), "l"(v0.x));
                asm("fma.rn.f32x2 %0, %1, %2, %0;" : "+l"(a10) : "l"(xa0), "l"(v1.x));
                asm("fma.rn.f32x2 %0, %1, %2, %0;" : "+l"(b00) : "l"(xb0), "l"(v0.x));
                asm("fma.rn.f32x2 %0, %1, %2, %0;" : "+l"(b10) : "l"(xb0), "l"(v1.x));
                asm("fma.rn.f32x2 %0, %1, %2, %0;" : "+l"(a01) : "l"(xa1), "l"(v0.y));
                asm("fma.rn.f32x2 %0, %1, %2, %0;" : "+l"(a11) : "l"(xa1), "l"(v1.y));
                asm("fma.rn.f32x2 %0, %1, %2, %0;" : "+l"(b01) : "l"(xb1), "l"(v0.y));
                asm("fma.rn.f32x2 %0, %1, %2, %0;" : "+l"(b11) : "l"(xb1), "l"(v1.y));
            }
            float t0, t1, t2, t3;
            float en0 = snorm[j], en1 = snorm[j + 1];

            // pos0, code j  — reduction order identical to R2
            asm("mov.b64 {%0, %1}, %2;" : "=f"(t0), "=f"(t1) : "l"(a00));
            asm("mov.b64 {%0, %1}, %2;" : "=f"(t2), "=f"(t3) : "l"(a01));
            float dot = (t0 + t1) + (t2 + t3);
            float d = __fsub_rn(__fadd_rn(xn0, en0), __fmul_rn(2.0f, dot));
            if (d < best0) { best0 = d; bi0 = c0 + j; }
            // pos0, code j+1
            asm("mov.b64 {%0, %1}, %2;" : "=f"(t0), "=f"(t1) : "l"(a10));
            asm("mov.b64 {%0, %1}, %2;" : "=f"(t2), "=f"(t3) : "l"(a11));
            dot = (t0 + t1) + (t2 + t3);
            d = __fsub_rn(__fadd_rn(xn0, en1), __fmul_rn(2.0f, dot));
            if (d < best0) { best0 = d; bi0 = c0 + j + 1; }
            // pos1, code j
            asm("mov.b64 {%0, %1}, %2;" : "=f"(t0), "=f"(t1) : "l"(b00));
            asm("mov.b64 {%0, %1}, %2;" : "=f"(t2), "=f"(t3) : "l"(b01));
            dot = (t0 + t1) + (t2 + t3);
            d = __fsub_rn(__fadd_rn(xn1, en0), __fmul_rn(2.0f, dot));
            if (d < best1) { best1 = d; bi1 = c0 + j; }
            // pos1, code j+1
            asm("mov.b64 {%0, %1}, %2;" : "=f"(t0), "=f"(t1) : "l"(b10));
            asm("mov.b64 {%0, %1}, %2;" : "=f"(t2), "=f"(t3) : "l"(b11));
            dot = (t0 + t1) + (t2 + t3);
            d = __fsub_rn(__fadd_rn(xn1, en1), __fmul_rn(2.0f, dot));
            if (d < best1) { best1 = d; bi1 = c0 + j + 1; }
        }
        __syncthreads();
    }

    // Gather winning codes (L2-resident) and scatter channel-strided.
    const float4* er0 = reinterpret_cast<const float4*>(emb + bi0 * EMBED_DIM);
    const float4* er1 = reinterpret_cast<const float4*>(emb + bi1 * EMBED_DIM);
#pragma unroll
    for (int k = 0; k < EMBED_DIM / 4; k++) {
        float4 v = er0[k];
        out[base0 + (4 * k + 0) * SPATIAL] = v.x;
        out[base0 + (4 * k + 1) * SPATIAL] = v.y;
        out[base0 + (4 * k + 2) * SPATIAL] = v.z;
        out[base0 + (4 * k + 3) * SPATIAL] = v.w;
        float4 w = er1[k];
        out[base1 + (4 * k + 0) * SPATIAL] = w.x;
        out[base1 + (4 * k + 1) * SPATIAL] = w.y;
        out[base1 + (4 * k + 2) * SPATIAL] = w.z;
        out[base1 + (4 * k + 3) * SPATIAL] = w.w;
    }
}

// --------------------------------------------------------------------------
extern "C" void kernel_launch(void* const* d_in, const int* in_sizes, int n_in,
                              void* d_out, int out_size) {
    const float* z   = (const float*)d_in[0];
    const float* emb = (const float*)d_in[1];
    // robustness: identify codebook by element count (1024*64 = 65536)
    if (n_in >= 2 && in_sizes[0] == EMBED_NUM * EMBED_DIM &&
        in_sizes[1] != EMBED_NUM * EMBED_DIM) {
        z   = (const float*)d_in[1];
        emb = (const float*)d_in[0];
    }
    float* out = (float*)d_out;

    vq_norms_kernel<<<(EMBED_NUM + 255) / 256, 256>>>(emb);
    vq_argmin_kernel<<<NVEC / (THREADS * PPT), THREADS>>>(z, emb, out);
}

// round 4
// speedup vs baseline: 1.2983x; 1.0001x over previous
#include <cuda_runtime.h>

#define EMBED_NUM 1024
#define EMBED_DIM 64
#define SPATIAL   32768          // 32*32*32
#define BATCH     4
#define NVEC      (BATCH * SPATIAL)   // 131072
#define CHUNK     128            // codes per smem tile (32 KB)
#define THREADS   128
#define PPT       2              // positions per thread (register-blocked)

__device__ float g_norms[EMBED_NUM];

// --------------------------------------------------------------------------
// Pre-pass: ||e_j||^2 for every codebook row (plain fp32 sequential sum).
// --------------------------------------------------------------------------
__global__ void vq_norms_kernel(const float* __restrict__ emb) {
    int j = blockIdx.x * blockDim.x + threadIdx.x;
    if (j < EMBED_NUM) {
        const float4* row = reinterpret_cast<const float4*>(emb + j * EMBED_DIM);
        float s = 0.f;
#pragma unroll
        for (int k = 0; k < EMBED_DIM / 4; k++) {
            float4 v = row[k];
            s += v.x * v.x + v.y * v.y + v.z * v.z + v.w * v.w;
        }
        g_norms[j] = s;
    }
}

// --------------------------------------------------------------------------
// Main kernel: one thread handles PPT=2 spatial positions.
//   Each code float4 loaded from smem now feeds 2 positions' dot products:
//   LDS instructions per FMA halve vs R2 (which was L1-pipe-bound at 81%).
//   Distance replicates the JAX reference's fp32 rounding EXACTLY (same
//   chain structure and reduction order as the R2 kernel, rel_err == 0.0):
//       d = fsub_rn( fadd_rn(xnorm, ||e||^2), fmul_rn(2, dot) )
// --------------------------------------------------------------------------
__global__ __launch_bounds__(THREADS, 2)
void vq_argmin_kernel(const float* __restrict__ z,
                      const float* __restrict__ emb,
                      float* __restrict__ out) {
    __shared__ float4 se[CHUNK][EMBED_DIM / 4];   // 32 KB
    __shared__ float  snorm[CHUNK];

    // Block covers 256 consecutive positions; thread t owns t and t+128.
    // 256 | 32768 so both positions are always in the same batch.
    const int p0 = blockIdx.x * (THREADS * PPT) + threadIdx.x;
    const int p1 = p0 + THREADS;
    const int b  = p0 >> 15;
    const int base0 = b * (EMBED_DIM * SPATIAL) + (p0 & (SPATIAL - 1));
    const int base1 = b * (EMBED_DIM * SPATIAL) + (p1 & (SPATIAL - 1));

    // Load both positions' 64-dim vectors (coalesced channel-strided loads),
    // pack into f32x2 registers, compute ||x||^2 each.
    unsigned long long x0[EMBED_DIM / 2], x1[EMBED_DIM / 2];
    float xn0 = 0.f, xn1 = 0.f;
#pragma unroll
    for (int k = 0; k < EMBED_DIM; k += 2) {
        float a = z[base0 + k * SPATIAL];
        float c = z[base0 + (k + 1) * SPATIAL];
        xn0 = __fadd_rn(xn0, __fmul_rn(a, a));
        xn0 = __fadd_rn(xn0, __fmul_rn(c, c));
        asm("mov.b64 %0, {%1, %2};" : "=l"(x0[k >> 1]) : "f"(a), "f"(c));
        float d = z[base1 + k * SPATIAL];
        float e = z[base1 + (k + 1) * SPATIAL];
        xn1 = __fadd_rn(xn1, __fmul_rn(d, d));
        xn1 = __fadd_rn(xn1, __fmul_rn(e, e));
        asm("mov.b64 %0, {%1, %2};" : "=l"(x1[k >> 1]) : "f"(d), "f"(e));
    }

    float best0 = 3.4e38f, best1 = 3.4e38f;
    int   bi0 = 0, bi1 = 0;

    for (int c0 = 0; c0 < EMBED_NUM; c0 += CHUNK) {
        // Cooperative chunk load: 2048 float4, 16 per thread.
        {
            const float4* src = reinterpret_cast<const float4*>(emb + c0 * EMBED_DIM);
            float4* dst = &se[0][0];
#pragma unroll
            for (int i = threadIdx.x; i < CHUNK * (EMBED_DIM / 4); i += THREADS)
                dst[i] = src[i];
            if (threadIdx.x < CHUNK)
                snorm[threadIdx.x] = g_norms[c0 + threadIdx.x];
        }
        __syncthreads();

#pragma unroll 1
        for (int j = 0; j < CHUNK; j += 2) {
            const ulonglong2* e0 = reinterpret_cast<const ulonglong2*>(&se[j][0]);
            const ulonglong2* e1 = reinterpret_cast<const ulonglong2*>(&se[j + 1][0]);
            // acc[pos][code][half]
            unsigned long long a00 = 0ULL, a01 = 0ULL;  // pos0, code j
            unsigned long long a10 = 0ULL, a11 = 0ULL;  // pos0, code j+1
            unsigned long long b00 = 0ULL, b01 = 0ULL;  // pos1, code j
            unsigned long long b10 = 0ULL, b11 = 0ULL;  // pos1, code j+1
#pragma unroll
            for (int q = 0; q < EMBED_DIM / 4; q++) {  // 16 iterations
                ulonglong2 v0 = e0[q];                 // LDS.128 broadcast
                ulonglong2 v1 = e1[q];
                unsigned long long xa0 = x0[2 * q], xa1 = x0[2 * q + 1];
                unsigned long long xb0 = x1[2 * q], xb1 = x1[2 * q + 1];
                asm("fma.rn.f32x2 %0, %1, %2, %0;" : "+l"(a00) : "l"(xa0), "l"(v0.x));
                asm("fma.rn.f32x2 %0, %1, %2, %0;" : "+l"(a10) : "l"(xa0), "l"(v1.x));
                asm("fma.rn.f32x2 %0, %1, %2, %0;" : "+l"(b00) : "l"(xb0), "l"(v0.x));
                asm("fma.rn.f32x2 %0, %1, %2, %0;" : "+l"(b10) : "l"(xb0), "l"(v1.x));
                asm("fma.rn.f32x2 %0, %1, %2, %0;" : "+l"(a01) : "l"(xa1), "l"(v0.y));
                asm("fma.rn.f32x2 %0, %1, %2, %0;" : "+l"(a11) : "l"(xa1), "l"(v1.y));
                asm("fma.rn.f32x2 %0, %1, %2, %0;" : "+l"(b01) : "l"(xb1), "l"(v0.y));
                asm("fma.rn.f32x2 %0, %1, %2, %0;" : "+l"(b11) : "l"(xb1), "l"(v1.y));
            }
            float t0, t1, t2, t3;
            float en0 = snorm[j], en1 = snorm[j + 1];

            // pos0, code j  — reduction order identical to R2
            asm("mov.b64 {%0, %1}, %2;" : "=f"(t0), "=f"(t1) : "l"(a00));
            asm("mov.b64 {%0, %1}, %2;" : "=f"(t2), "=f"(t3) : "l"(a01));
            float dot = (t0 + t1) + (t2 + t3);
            float d = __fsub_rn(__fadd_rn(xn0, en0), __fmul_rn(2.0f, dot));
            if (d < best0) { best0 = d; bi0 = c0 + j; }
            // pos0, code j+1
            asm("mov.b64 {%0, %1}, %2;" : "=f"(t0), "=f"(t1) : "l"(a10));
            asm("mov.b64 {%0, %1}, %2;" : "=f"(t2), "=f"(t3) : "l"(a11));
            dot = (t0 + t1) + (t2 + t3);
            d = __fsub_rn(__fadd_rn(xn0, en1), __fmul_rn(2.0f, dot));
            if (d < best0) { best0 = d; bi0 = c0 + j + 1; }
            // pos1, code j
            asm("mov.b64 {%0, %1}, %2;" : "=f"(t0), "=f"(t1) : "l"(b00));
            asm("mov.b64 {%0, %1}, %2;" : "=f"(t2), "=f"(t3) : "l"(b01));
            dot = (t0 + t1) + (t2 + t3);
            d = __fsub_rn(__fadd_rn(xn1, en0), __fmul_rn(2.0f, dot));
            if (d < best1) { best1 = d; bi1 = c0 + j; }
            // pos1, code j+1
            asm("mov.b64 {%0, %1}, %2;" : "=f"(t0), "=f"(t1) : "l"(b10));
            asm("mov.b64 {%0, %1}, %2;" : "=f"(t2), "=f"(t3) : "l"(b11));
            dot = (t0 + t1) + (t2 + t3);
            d = __fsub_rn(__fadd_rn(xn1, en1), __fmul_rn(2.0f, dot));
            if (d < best1) { best1 = d; bi1 = c0 + j + 1; }
        }
        __syncthreads();
    }

    // Gather winning codes (L2-resident) and scatter channel-strided.
    const float4* er0 = reinterpret_cast<const float4*>(emb + bi0 * EMBED_DIM);
    const float4* er1 = reinterpret_cast<const float4*>(emb + bi1 * EMBED_DIM);
#pragma unroll
    for (int k = 0; k < EMBED_DIM / 4; k++) {
        float4 v = er0[k];
        out[base0 + (4 * k + 0) * SPATIAL] = v.x;
        out[base0 + (4 * k + 1) * SPATIAL] = v.y;
        out[base0 + (4 * k + 2) * SPATIAL] = v.z;
        out[base0 + (4 * k + 3) * SPATIAL] = v.w;
        float4 w = er1[k];
        out[base1 + (4 * k + 0) * SPATIAL] = w.x;
        out[base1 + (4 * k + 1) * SPATIAL] = w.y;
        out[base1 + (4 * k + 2) * SPATIAL] = w.z;
        out[base1 + (4 * k + 3) * SPATIAL] = w.w;
    }
}

// --------------------------------------------------------------------------
extern "C" void kernel_launch(void* const* d_in, const int* in_sizes, int n_in,
                              void* d_out, int out_size) {
    const float* z   = (const float*)d_in[0];
    const float* emb = (const float*)d_in[1];
    // robustness: identify codebook by element count (1024*64 = 65536)
    if (n_in >= 2 && in_sizes[0] == EMBED_NUM * EMBED_DIM &&
        in_sizes[1] != EMBED_NUM * EMBED_DIM) {
        z   = (const float*)d_in[1];
        emb = (const float*)d_in[0];
    }
    float* out = (float*)d_out;

    vq_norms_kernel<<<(EMBED_NUM + 255) / 256, 256>>>(emb);
    vq_argmin_kernel<<<NVEC / (THREADS * PPT), THREADS>>>(z, emb, out);
}